// round 2
// baseline (speedup 1.0000x reference)
#include <cuda_runtime.h>
#include <cuda_bf16.h>

// AdderVDSR collapses analytically:
//   adder_conv output = -sum of 576 |.| terms  <= 0  (strictly < 0 on this data)
//   relu(negative) == 0 exactly  =>  h == 0 after the first adder block,
//   and stays 0 through all 16 scanned blocks.
// Hence:
//   out[b,c,:,:] = pixel_shuffle(conv3x3(x, up_w) + up_b, r=2) + out_b[c]
//
// Inputs (metadata order): x[2,3,128,128], up_w[12,3,3,3], up_b[12],
//   in_w, in_b, adder_w, out_w, out_b[3].  Output: [2,3,256,256] fp32.
//
// One (b, o=4c+2p+q) conv value at (i,j) maps to out[b, c, 2i+p, 2j+q].
//
// R1 bug: weight load used `if (tid < 324)` with only 256 threads ->
// sw[256..323] uninitialized (rel_err 0.43). Fixed with a strided loop.

#define TILE 16
#define HIN 128
#define WIN 128

__global__ __launch_bounds__(256) void adder_vdsr_collapsed(
    const float* __restrict__ x,      // [2,3,128,128]
    const float* __restrict__ up_w,   // [12,3,3,3] = 324
    const float* __restrict__ up_b,   // [12]
    const float* __restrict__ out_b,  // [3]
    float* __restrict__ out)          // [2,3,256,256]
{
    __shared__ float sw[324];
    __shared__ float sb[12];
    __shared__ float sob[3];
    __shared__ float sx[3][TILE + 2][TILE + 2];

    const int b  = blockIdx.z;
    const int ti = blockIdx.y * TILE;
    const int tj = blockIdx.x * TILE;
    const int tx = threadIdx.x, ty = threadIdx.y;
    const int tid = ty * TILE + tx;

    // 324 > 256 threads: strided load (2 iterations).
    #pragma unroll
    for (int k = tid; k < 324; k += 256) sw[k] = up_w[k];
    if (tid < 12)  sb[tid]  = up_b[tid];
    if (tid < 3)   sob[tid] = out_b[tid];

    // Input tile with 1-px halo: rows [ti-1, ti+16], cols [tj-1, tj+16], 3 channels.
    #pragma unroll
    for (int c = 0; c < 3; c++) {
        #pragma unroll
        for (int idx = tid; idx < 18 * 18; idx += 256) {
            int r  = idx / 18;
            int cc = idx - r * 18;
            int gi = ti - 1 + r;
            int gj = tj - 1 + cc;
            float v = 0.0f;
            if (gi >= 0 && gi < HIN && gj >= 0 && gj < WIN)
                v = x[((b * 3 + c) * HIN + gi) * WIN + gj];
            sx[c][r][cc] = v;
        }
    }
    __syncthreads();

    const int i = ti + ty;
    const int j = tj + tx;

    float acc[12];
    #pragma unroll
    for (int o = 0; o < 12; o++) acc[o] = sb[o];

    #pragma unroll
    for (int c = 0; c < 3; c++) {
        #pragma unroll
        for (int ki = 0; ki < 3; ki++) {
            #pragma unroll
            for (int kj = 0; kj < 3; kj++) {
                const float v = sx[c][ty + ki][tx + kj];
                #pragma unroll
                for (int o = 0; o < 12; o++)
                    acc[o] = fmaf(v, sw[((o * 3 + c) * 3 + ki) * 3 + kj], acc[o]);
            }
        }
    }

    // Pixel shuffle scatter: o = 4c + 2p + q -> out[b, c, 2i+p, 2j+q].
    // (2j, 2j+1) is contiguous -> float2 stores.
    #pragma unroll
    for (int c = 0; c < 3; c++) {
        const float bias = sob[c];
        #pragma unroll
        for (int p = 0; p < 2; p++) {
            float2 v;
            v.x = acc[4 * c + 2 * p + 0] + bias;
            v.y = acc[4 * c + 2 * p + 1] + bias;
            float* row = out + ((size_t)(b * 3 + c) * 256 + (2 * i + p)) * 256;
            reinterpret_cast<float2*>(row)[j] = v;
        }
    }
}

extern "C" void kernel_launch(void* const* d_in, const int* in_sizes, int n_in,
                              void* d_out, int out_size) {
    (void)in_sizes; (void)n_in; (void)out_size;
    const float* x     = (const float*)d_in[0];
    const float* up_w  = (const float*)d_in[1];
    const float* up_b  = (const float*)d_in[2];
    const float* out_b = (const float*)d_in[7];
    float* out = (float*)d_out;

    dim3 grid(WIN / TILE, HIN / TILE, 2);   // (8, 8, 2)
    dim3 block(TILE, TILE);                 // 256 threads
    adder_vdsr_collapsed<<<grid, block>>>(x, up_w, up_b, out_b, out);
}

// round 4
// speedup vs baseline: 1.3478x; 1.3478x over previous
#include <cuda_runtime.h>
#include <cuda_bf16.h>

// AdderVDSR collapses analytically (see R0-R2):
//   relu(adder_conv) == 0 exactly after block 1 (sum of 576 |.| is strictly
//   negative pre-negation), so all 16 adder blocks emit zeros and
//   out[b,c] = out_b[c] + pixel_shuffle(conv3x3(x, up_w) + up_b, r=2).
//
// R3 layout: one CTA owns a fixed (batch b, out color c, row parity p) ->
// exactly 2 conv channels {4c+2p, 4c+2p+1}. Their 54 weights are CTA-uniform
// and live in REGISTERS (no LDS in the FFMA loop, no smem, no barrier).
// One thread produces one float4 of the output row:
//   out cols 4tx..4tx+3 = conv[{o0,o1}, i, {2tx, 2tx+1}] interleaved by the
//   pixel shuffle. 36 input __ldg's (L2-resident), 108 FFMA, 1 STG.128.

__global__ __launch_bounds__(256) void adder_vdsr_collapsed(
    const float* __restrict__ x,      // [2,3,128,128]
    const float* __restrict__ up_w,   // [12,3,3,3]
    const float* __restrict__ up_b,   // [12]
    const float* __restrict__ out_b,  // [3]
    float* __restrict__ out)          // [2,3,256,256]
{
    const int tx = threadIdx.x;                 // 0..63  -> conv col pair 2tx
    const int ty = threadIdx.y;                 // 0..3
    const int i  = blockIdx.y * 4 + ty;         // conv row 0..127
    const int z  = blockIdx.z;                  // 0..11
    const int b  = z / 6;
    const int cp = z % 6;
    const int c  = cp >> 1;
    const int p  = cp & 1;
    const int o0 = 4 * c + 2 * p;

    // 54 CTA-uniform weights -> registers (uniform __ldg, L1 broadcast).
    float w0[27], w1[27];
    const float* W = up_w + o0 * 27;
    #pragma unroll
    for (int k = 0; k < 27; k++) {
        w0[k] = __ldg(W + k);
        w1[k] = __ldg(W + 27 + k);
    }
    const float bias0 = __ldg(up_b + o0);
    const float bias1 = __ldg(up_b + o0 + 1);
    const float ob    = __ldg(out_b + c);

    float a00 = bias0, a01 = bias0;   // channel o0, px {2tx, 2tx+1}
    float a10 = bias1, a11 = bias1;   // channel o1

    const int j0 = 2 * tx;

    #pragma unroll
    for (int cin = 0; cin < 3; cin++) {
        const float* xp = x + (size_t)(b * 3 + cin) * 128 * 128;
        float v[3][4];
        #pragma unroll
        for (int ki = 0; ki < 3; ki++) {
            const int gi = i - 1 + ki;
            const bool rok = (gi >= 0) & (gi < 128);
            #pragma unroll
            for (int kc = 0; kc < 4; kc++) {
                const int gj = j0 - 1 + kc;
                v[ki][kc] = (rok && gj >= 0 && gj < 128)
                          ? __ldg(xp + gi * 128 + gj) : 0.0f;
            }
        }
        #pragma unroll
        for (int ki = 0; ki < 3; ki++) {
            #pragma unroll
            for (int kj = 0; kj < 3; kj++) {
                const float wv0 = w0[cin * 9 + ki * 3 + kj];
                const float wv1 = w1[cin * 9 + ki * 3 + kj];
                a00 = fmaf(v[ki][kj],     wv0, a00);
                a10 = fmaf(v[ki][kj],     wv1, a10);
                a01 = fmaf(v[ki][kj + 1], wv0, a01);
                a11 = fmaf(v[ki][kj + 1], wv1, a11);
            }
        }
    }

    // Pixel-shuffle interleave: [o0@2tx, o1@2tx, o0@2tx+1, o1@2tx+1]
    float4 r = make_float4(a00 + ob, a10 + ob, a01 + ob, a11 + ob);
    float* row = out + ((size_t)(b * 3 + c) * 256 + (2 * i + p)) * 256;
    reinterpret_cast<float4*>(row)[tx] = r;
}

extern "C" void kernel_launch(void* const* d_in, const int* in_sizes, int n_in,
                              void* d_out, int out_size) {
    (void)in_sizes; (void)n_in; (void)out_size;
    const float* x     = (const float*)d_in[0];
    const float* up_w  = (const float*)d_in[1];
    const float* up_b  = (const float*)d_in[2];
    const float* out_b = (const float*)d_in[7];
    float* out = (float*)d_out;

    dim3 grid(1, 32, 12);   // 384 CTAs: y = i/4, z = b*6 + (c*2+p)
    dim3 block(64, 4);      // 256 threads; tx = conv-col pair, ty = row
    adder_vdsr_collapsed<<<grid, block>>>(x, up_w, up_b, out_b, out);
}